// round 14
// baseline (speedup 1.0000x reference)
#include <cuda_runtime.h>

#define NB 16
#define ND 64
#define NN 200
#define NT 48
#define NH 8

// intermediate h = x^T + LN(temporal_out):  (B,N,T,D)
__device__ float g_h[NB * NN * NT * ND];

// pre-transposed weights (written by prep_weights each launch)
__device__ float2 g_wqkT[192 * 64];   // [(e*3+k)][d] -> (Wq, Wk)
__device__ float  g_w1T[64 * 64];     // [e][d] = W1[d][e]

__global__ void prep_weights(const float* __restrict__ Wq,
                             const float* __restrict__ Wk,
                             const float* __restrict__ W1)
{
    int i = blockIdx.x * 256 + threadIdx.x;
    if (i < 12288) {
        int r = i >> 6, d = i & 63;          // r = e*3+k
        float2 v;
        v.x = Wq[d * 192 + r];
        v.y = Wk[d * 192 + r];
        g_wqkT[i] = v;
    }
    if (i < 4096) {
        int e = i >> 6, d = i & 63;
        g_w1T[i] = W1[d * 64 + e];
    }
}

// ---- packed f32x2 helpers (Blackwell FFMA2 via PTX) ----
__device__ __forceinline__ float2 ffma2(float2 a, float2 b, float2 c) {
    float2 d;
    asm("fma.rn.f32x2 %0, %1, %2, %3;"
        : "=l"(*reinterpret_cast<unsigned long long*>(&d))
        : "l"(*reinterpret_cast<const unsigned long long*>(&a)),
          "l"(*reinterpret_cast<const unsigned long long*>(&b)),
          "l"(*reinterpret_cast<const unsigned long long*>(&c)));
    return d;
}
__device__ __forceinline__ float2 fdup(float s) { return make_float2(s, s); }
__device__ __forceinline__ float2 f2lo(float4 v) { return make_float2(v.x, v.y); }
__device__ __forceinline__ float2 f2hi(float4 v) { return make_float2(v.z, v.w); }

// ---------------------------------------------------------------------------
// Kernel 1: per (b, n). Fused conv1x3 q/k + v (single pass, packed f32x2),
// 8-head attention over T=48 (rows in registers, packed), W2 projection
// (packed dot over e), LayerNorm + residual -> g_h.
// smem floats: xs[64][52]@0, qs[64][52]@3328, ks[64][52]@6656, vs[48][68]@9984,
//              aos[48][68]@13248, ys[48][68]@16512, w2s[64][68]@19776
//              => 24128 floats = 96512 B  (2 blocks/SM)
// ---------------------------------------------------------------------------
__global__ void __launch_bounds__(256, 2) temporal_kernel(
    const float* __restrict__ x,  const float* __restrict__ W2,
    const float* __restrict__ bq, const float* __restrict__ bk,
    const float* __restrict__ b1, const float* __restrict__ b2,
    const float* __restrict__ g0, const float* __restrict__ beta0)
{
    extern __shared__ float sm[];
    float* xs   = sm;            // [64][52], col0/col49 zero pad
    float* qs   = sm + 3328;     // [64][52]
    float* ks   = sm + 6656;     // [64][52]
    float* vs   = sm + 9984;     // [48][68]
    float* aos  = sm + 13248;    // [48][68]
    float* ys   = sm + 16512;    // [48][68]
    float* w2s  = sm + 19776;    // [64][68]  W2 rows (row-major)

    const int n   = blockIdx.x;
    const int b   = blockIdx.y;
    const int tid = threadIdx.x;
    const int d   = tid & 63;
    const int t0  = (tid >> 6) * 12;
    const int lane = tid & 31;
    const int warp = tid >> 5;

    // load x tile: x[b][e][n][t] -> xs[e][1+t]
    const float* xbase = x + ((long)(b * 64) * 200 + n) * 48;
    for (int i = tid; i < 64 * 48; i += 256) {
        int e = i / 48, t = i % 48;
        xs[e * 52 + 1 + t] = xbase[(long)e * 9600 + t];
    }
    if (tid < 128) {
        int e = tid & 63;
        xs[e * 52 + ((tid < 64) ? 0 : 49)] = 0.f;
    }
    // stage W2 rows into smem (row-major, stride 68)
    for (int i = tid; i < 1024; i += 256) {
        int dd = i >> 4, e0 = (i & 15) * 4;
        *(float4*)(w2s + dd * 68 + e0) = *(const float4*)(W2 + dd * 64 + e0);
    }
    __syncthreads();   // xs, w2s ready

    // ---- fused conv1x3 q/k (packed over (q,k)) + v (scalar), single pass
    float2 qk[12];
    float  va[12];
    #pragma unroll
    for (int j = 0; j < 12; j++) { qk[j] = make_float2(0.f, 0.f); va[j] = 0.f; }

    #pragma unroll 2
    for (int el = 0; el < 64; el++) {
        const float2* wr = g_wqkT + el * 192 + d;
        float2 w0 = __ldg(wr);
        float2 w1 = __ldg(wr + 64);
        float2 w2 = __ldg(wr + 128);
        float  wv = __ldg(g_w1T + el * 64 + d);
        const float* xp = xs + el * 52 + t0;   // aligned; taps at [0..13]
        float4 x0 = *(const float4*)(xp);
        float4 x1 = *(const float4*)(xp + 4);
        float4 x2 = *(const float4*)(xp + 8);
        float4 x3 = *(const float4*)(xp + 12);
        float xv[16] = {x0.x,x0.y,x0.z,x0.w, x1.x,x1.y,x1.z,x1.w,
                        x2.x,x2.y,x2.z,x2.w, x3.x,x3.y,x3.z,x3.w};
        float2 xd[14];
        #pragma unroll
        for (int j = 0; j < 14; j++) xd[j] = fdup(xv[j]);
        #pragma unroll
        for (int j = 0; j < 12; j++) {
            qk[j] = ffma2(xd[j],     w0, qk[j]);
            qk[j] = ffma2(xd[j + 1], w1, qk[j]);
            qk[j] = ffma2(xd[j + 2], w2, qk[j]);
            va[j] += wv * xv[j + 1];
        }
    }
    {
        float bqv = __ldg(bq + d), bkv = __ldg(bk + d), b1v = __ldg(b1 + d);
        #pragma unroll
        for (int j = 0; j < 12; j++) {
            qs[d * 52 + t0 + j] = qk[j].x + bqv;
            ks[d * 52 + t0 + j] = qk[j].y + bkv;
            vs[(t0 + j) * 68 + d] = va[j] + b1v;
        }
    }
    __syncthreads();   // qs, ks, vs ready

    // ---- attention: thread = (head-half, t); two sweeps of 4 heads
    const float scale = 0.35355339059327373f; // 1/sqrt(8)
    if (tid < 192) {
        const int t  = tid % 48;
        const int hh = tid / 48;       // 0..3
        #pragma unroll
        for (int sw = 0; sw < 2; sw++) {
            const int hd = (sw * 4 + hh) * 8;
            float2 qd[8];
            #pragma unroll
            for (int dk = 0; dk < 8; dk++)
                qd[dk] = fdup(qs[(hd + dk) * 52 + t] * scale);
            float2 s2[24];
            #pragma unroll
            for (int i = 0; i < 24; i++) s2[i] = make_float2(0.f, 0.f);
            #pragma unroll
            for (int u4 = 0; u4 < 12; u4++) {
                #pragma unroll
                for (int dk = 0; dk < 8; dk++) {
                    float4 kv = *(const float4*)(ks + (hd + dk) * 52 + u4 * 4);
                    s2[2 * u4]     = ffma2(qd[dk], f2lo(kv), s2[2 * u4]);
                    s2[2 * u4 + 1] = ffma2(qd[dk], f2hi(kv), s2[2 * u4 + 1]);
                }
            }
            // softmax in registers
            float mx = -1e30f;
            #pragma unroll
            for (int i = 0; i < 24; i++)
                mx = fmaxf(mx, fmaxf(s2[i].x, s2[i].y));
            float sum = 0.f;
            #pragma unroll
            for (int i = 0; i < 24; i++) {
                s2[i].x = __expf(s2[i].x - mx);
                s2[i].y = __expf(s2[i].y - mx);
                sum += s2[i].x + s2[i].y;
            }
            float inv = 1.f / sum;
            // PV (packed over d)
            float2 a0l = make_float2(0.f, 0.f), a0h = a0l, a1l = a0l, a1h = a0l;
            #pragma unroll
            for (int i = 0; i < 24; i++) {
                int u = 2 * i;
                float2 p0 = fdup(s2[i].x), p1 = fdup(s2[i].y);
                float4 v00 = *(const float4*)(vs + u * 68 + hd);
                float4 v01 = *(const float4*)(vs + u * 68 + hd + 4);
                float4 v10 = *(const float4*)(vs + (u + 1) * 68 + hd);
                float4 v11 = *(const float4*)(vs + (u + 1) * 68 + hd + 4);
                a0l = ffma2(p0, f2lo(v00), a0l); a0h = ffma2(p0, f2hi(v00), a0h);
                a1l = ffma2(p0, f2lo(v01), a1l); a1h = ffma2(p0, f2hi(v01), a1h);
                a0l = ffma2(p1, f2lo(v10), a0l); a0h = ffma2(p1, f2hi(v10), a0h);
                a1l = ffma2(p1, f2lo(v11), a1l); a1h = ffma2(p1, f2hi(v11), a1h);
            }
            float4 o0 = make_float4(a0l.x * inv, a0l.y * inv, a0h.x * inv, a0h.y * inv);
            float4 o1 = make_float4(a1l.x * inv, a1l.y * inv, a1h.x * inv, a1h.y * inv);
            *(float4*)(aos + t * 68 + hd)     = o0;
            *(float4*)(aos + t * 68 + hd + 4) = o1;
        }
    }
    __syncthreads();

    // ---- y = ao @ W2^T + b2 (packed dot over e)
    {
        float2 ya2[12];
        #pragma unroll
        for (int j = 0; j < 12; j++) ya2[j] = make_float2(0.f, 0.f);
        #pragma unroll 4
        for (int e0 = 0; e0 < 64; e0 += 4) {
            float4 w = *(const float4*)(w2s + d * 68 + e0);
            float2 wl = f2lo(w), wh = f2hi(w);
            #pragma unroll
            for (int j = 0; j < 12; j++) {
                float4 a = *(const float4*)(aos + (t0 + j) * 68 + e0);
                ya2[j] = ffma2(wl, f2lo(a), ya2[j]);
                ya2[j] = ffma2(wh, f2hi(a), ya2[j]);
            }
        }
        float b2v = __ldg(b2 + d);
        #pragma unroll
        for (int j = 0; j < 12; j++)
            ys[(t0 + j) * 68 + d] = ya2[j].x + ya2[j].y + b2v;
    }
    __syncthreads();

    // ---- LayerNorm over d + residual x^T -> g_h
    float* hout = g_h + ((long)(b * 200 + n)) * 48 * 64;
    for (int t = warp; t < 48; t += 8) {
        float y1 = ys[t * 68 + lane];
        float y2 = ys[t * 68 + lane + 32];
        float s = y1 + y2;
        #pragma unroll
        for (int o = 16; o > 0; o >>= 1) s += __shfl_xor_sync(0xffffffffu, s, o);
        float mean = s * (1.f / 64.f);
        float d1 = y1 - mean, d2 = y2 - mean;
        float vv = d1 * d1 + d2 * d2;
        #pragma unroll
        for (int o = 16; o > 0; o >>= 1) vv += __shfl_xor_sync(0xffffffffu, vv, o);
        float rstd = rsqrtf(vv * (1.f / 64.f) + 1e-5f);
        float h1 = xs[lane * 52 + 1 + t]        + d1 * rstd * __ldg(g0 + lane)      + __ldg(beta0 + lane);
        float h2 = xs[(lane + 32) * 52 + 1 + t] + d2 * rstd * __ldg(g0 + lane + 32) + __ldg(beta0 + lane + 32);
        hout[t * 64 + lane]      = h1;
        hout[t * 64 + lane + 32] = h2;
    }
}

// ---------------------------------------------------------------------------
// Kernel 2: per (b, t, rowhalf). Spatial softmax-GCN, 100 rows/block.
// Packed f32x2 everywhere: scores/Theta = dot-over-dd pairs, agg = dup(P)*h.
// Softmax without max-shift; lane-local row-sums reduced once at the end.
// smem floats: hs[200][68]@0 (13600), S[100][68]@13600 (6800; ThS[64][68]
// overlays) => 20400 floats = 81600 B  (2 blocks/SM)
// ---------------------------------------------------------------------------
__global__ void __launch_bounds__(256, 2) spatial_kernel(
    const float* __restrict__ adj, const float* __restrict__ Theta,
    const float* __restrict__ g1,  const float* __restrict__ beta1,
    float* __restrict__ out)
{
    extern __shared__ float sm[];
    float* hs = sm;            // [200][68]
    float* S  = sm + 13600;    // [100][68] P buffer; later ThS[64][68] dd-major

    const int t = blockIdx.x, b = blockIdx.y;
    const int r0 = blockIdx.z * 100;
    const int tid = threadIdx.x;
    const int tx = tid & 15, ty = tid >> 4;

    const float* hbase = g_h + (long)b * 200 * 48 * 64 + (long)t * 64;
    for (int i = tid; i < 3200; i += 256) {
        int nn = i >> 4, d4 = (i & 15) * 4;
        *(float4*)(hs + nn * 68 + d4) = *(const float4*)(hbase + (long)nn * 3072 + d4);
    }

    int  nl[7], slc[7];
    bool rv[7];
    #pragma unroll
    for (int r = 0; r < 7; r++) {
        int v = ty + 16 * r;
        rv[r]  = (v < 100);
        slc[r] = rv[r] ? v : 99;
        nl[r]  = slc[r];
    }

    float2 agg2[7][2];
    float  rs[7];
    #pragma unroll
    for (int r = 0; r < 7; r++) {
        rs[r] = 0.f;
        agg2[r][0] = make_float2(0.f, 0.f);
        agg2[r][1] = make_float2(0.f, 0.f);
    }

    __syncthreads();   // hs ready

    for (int ci = 0; ci < 4; ci++) {
        const int m0 = ci * 64;
        const int MC = (ci == 3) ? 8 : 64;
        __syncwarp();  // P rows from previous chunk fully consumed

        // ---- scores (packed dot over dd): rows r0+nl[r], cols m0+tx+16c ----
        float2 sc2[7][4];
        #pragma unroll
        for (int r = 0; r < 7; r++)
            #pragma unroll
            for (int c = 0; c < 4; c++) sc2[r][c] = make_float2(0.f, 0.f);
        int  mc[4]; bool mv[4];
        #pragma unroll
        for (int c = 0; c < 4; c++) {
            int m = m0 + tx + 16 * c;
            mv[c] = (m < 200);
            mc[c] = mv[c] ? m : 199;
        }
        for (int dd = 0; dd < 64; dd += 4) {
            float4 bb[4];
            #pragma unroll
            for (int c = 0; c < 4; c++)
                bb[c] = *(const float4*)(hs + mc[c] * 68 + dd);
            #pragma unroll
            for (int r = 0; r < 7; r++) {
                float4 av = *(const float4*)(hs + (r0 + slc[r]) * 68 + dd);
                float2 al = f2lo(av), ah = f2hi(av);
                #pragma unroll
                for (int c = 0; c < 4; c++) {
                    sc2[r][c] = ffma2(al, f2lo(bb[c]), sc2[r][c]);
                    sc2[r][c] = ffma2(ah, f2hi(bb[c]), sc2[r][c]);
                }
            }
        }

        // ---- exp (no shift) + lane-local row-sum + P = e * adj ----
        #pragma unroll
        for (int r = 0; r < 7; r++) {
            float e[4];
            #pragma unroll
            for (int c = 0; c < 4; c++) {
                float sv = (sc2[r][c].x + sc2[r][c].y) * 0.125f;
                e[c] = mv[c] ? __expf(sv) : 0.f;
            }
            rs[r] += (e[0] + e[1]) + (e[2] + e[3]);
            if (rv[r]) {
                const float* arow = adj + (long)(r0 + nl[r]) * 200 + m0;
                #pragma unroll
                for (int c = 0; c < 4; c++)
                    if (mv[c])
                        S[nl[r] * 68 + tx + 16 * c] = e[c] * __ldg(arow + tx + 16 * c);
            }
        }
        __syncwarp();   // P rows visible within owning half-warp

        // ---- agg += P_chunk @ h_chunk (dup(P) * packed h, cols dd=4tx+c) ----
        for (int mb = 0; mb < MC; mb += 4) {
            float4 hb[4];
            #pragma unroll
            for (int j = 0; j < 4; j++)
                hb[j] = *(const float4*)(hs + (m0 + mb + j) * 68 + 4 * tx);
            #pragma unroll
            for (int r = 0; r < 7; r++) {
                float4 pw = *(const float4*)(S + slc[r] * 68 + mb);
                float2 p0 = fdup(pw.x), p1 = fdup(pw.y), p2 = fdup(pw.z), p3 = fdup(pw.w);
                agg2[r][0] = ffma2(p0, f2lo(hb[0]), agg2[r][0]);
                agg2[r][1] = ffma2(p0, f2hi(hb[0]), agg2[r][1]);
                agg2[r][0] = ffma2(p1, f2lo(hb[1]), agg2[r][0]);
                agg2[r][1] = ffma2(p1, f2hi(hb[1]), agg2[r][1]);
                agg2[r][0] = ffma2(p2, f2lo(hb[2]), agg2[r][0]);
                agg2[r][1] = ffma2(p2, f2hi(hb[2]), agg2[r][1]);
                agg2[r][0] = ffma2(p3, f2lo(hb[3]), agg2[r][0]);
                agg2[r][1] = ffma2(p3, f2hi(hb[3]), agg2[r][1]);
            }
        }
    }

    __syncthreads();   // done reading hs / S everywhere

    // reduce row-sums across the 16 lanes, finalize agg /= (rsum * sqrt(D))
    #pragma unroll
    for (int r = 0; r < 7; r++) {
        float s = rs[r];
        #pragma unroll
        for (int o = 8; o > 0; o >>= 1)
            s += __shfl_xor_sync(0xffffffffu, s, o, 16);
        float inv = 1.f / (s * 8.f);
        if (rv[r]) {
            float4 v = make_float4(agg2[r][0].x * inv, agg2[r][0].y * inv,
                                   agg2[r][1].x * inv, agg2[r][1].y * inv);
            *(float4*)(hs + nl[r] * 68 + 4 * tx) = v;
        }
    }
    // stage Theta dd-major: ThS[dd*68 + j] = Theta[j][dd]
    for (int i = tid; i < 4096; i += 256)
        S[(i & 63) * 68 + (i >> 6)] = Theta[i];
    __syncthreads();

    // G = relu(agg @ Theta^T): dup(agg) * packed Theta (lanes = j-pairs)
    float2 g2[7][2];
    #pragma unroll
    for (int r = 0; r < 7; r++) {
        g2[r][0] = make_float2(0.f, 0.f);
        g2[r][1] = make_float2(0.f, 0.f);
    }
    for (int dd = 0; dd < 64; dd += 4) {
        float4 tb[4];
        #pragma unroll
        for (int i = 0; i < 4; i++)
            tb[i] = *(const float4*)(S + (dd + i) * 68 + 4 * tx);
        #pragma unroll
        for (int r = 0; r < 7; r++) {
            float4 av = *(const float4*)(hs + slc[r] * 68 + dd);
            float2 a0 = fdup(av.x), a1 = fdup(av.y), a2 = fdup(av.z), a3 = fdup(av.w);
            g2[r][0] = ffma2(a0, f2lo(tb[0]), g2[r][0]);
            g2[r][1] = ffma2(a0, f2hi(tb[0]), g2[r][1]);
            g2[r][0] = ffma2(a1, f2lo(tb[1]), g2[r][0]);
            g2[r][1] = ffma2(a1, f2hi(tb[1]), g2[r][1]);
            g2[r][0] = ffma2(a2, f2lo(tb[2]), g2[r][0]);
            g2[r][1] = ffma2(a2, f2hi(tb[2]), g2[r][1]);
            g2[r][0] = ffma2(a3, f2lo(tb[3]), g2[r][0]);
            g2[r][1] = ffma2(a3, f2hi(tb[3]), g2[r][1]);
        }
    }
    float g[7][4];
    #pragma unroll
    for (int r = 0; r < 7; r++) {
        g[r][0] = fmaxf(g2[r][0].x, 0.f);
        g[r][1] = fmaxf(g2[r][0].y, 0.f);
        g[r][2] = fmaxf(g2[r][1].x, 0.f);
        g[r][3] = fmaxf(g2[r][1].y, 0.f);
    }

    // LayerNorm over j + residual (float4 gmem) + store
    float* obase = out + (long)b * 200 * 3072 + (long)t * 64;
    float4 g1v = *(const float4*)(g1 + 4 * tx);
    float4 b1v = *(const float4*)(beta1 + 4 * tx);
    #pragma unroll
    for (int r = 0; r < 7; r++) {
        if (!rv[r]) continue;
        int ng = r0 + nl[r];
        float s = g[r][0] + g[r][1] + g[r][2] + g[r][3];
        #pragma unroll
        for (int o = 8; o > 0; o >>= 1) s += __shfl_xor_sync(0xffffffffu, s, o, 16);
        float mean = s * (1.f / 64.f);
        float vv = 0.f;
        #pragma unroll
        for (int c = 0; c < 4; c++) { float dg = g[r][c] - mean; vv += dg * dg; }
        #pragma unroll
        for (int o = 8; o > 0; o >>= 1) vv += __shfl_xor_sync(0xffffffffu, vv, o, 16);
        float rstd = rsqrtf(vv * (1.f / 64.f) + 1e-5f);
        float4 hv = *(const float4*)(hbase + (long)ng * 3072 + 4 * tx);
        float4 ov;
        ov.x = hv.x + (g[r][0] - mean) * rstd * g1v.x + b1v.x;
        ov.y = hv.y + (g[r][1] - mean) * rstd * g1v.y + b1v.y;
        ov.z = hv.z + (g[r][2] - mean) * rstd * g1v.z + b1v.z;
        ov.w = hv.w + (g[r][3] - mean) * rstd * g1v.w + b1v.w;
        *(float4*)(obase + (long)ng * 3072 + 4 * tx) = ov;
    }
}

// ---------------------------------------------------------------------------
extern "C" void kernel_launch(void* const* d_in, const int* in_sizes, int n_in,
                              void* d_out, int out_size)
{
    const float* x     = (const float*)d_in[0];
    const float* adj   = (const float*)d_in[1];
    const float* Wq    = (const float*)d_in[2];
    const float* bq    = (const float*)d_in[3];
    const float* Wk    = (const float*)d_in[4];
    const float* bk    = (const float*)d_in[5];
    const float* W1    = (const float*)d_in[6];
    const float* b1    = (const float*)d_in[7];
    const float* W2    = (const float*)d_in[8];
    const float* b2    = (const float*)d_in[9];
    const float* Theta = (const float*)d_in[10];
    const float* g0    = (const float*)d_in[11];
    const float* beta0 = (const float*)d_in[12];
    const float* g1    = (const float*)d_in[13];
    const float* beta1 = (const float*)d_in[14];
    float* out = (float*)d_out;

    const int SMEM_T = 24128 * 4;   // 96512 B
    const int SMEM_S = 20400 * 4;   // 81600 B
    cudaFuncSetAttribute(temporal_kernel,
                         cudaFuncAttributeMaxDynamicSharedMemorySize, SMEM_T);
    cudaFuncSetAttribute(spatial_kernel,
                         cudaFuncAttributeMaxDynamicSharedMemorySize, SMEM_S);

    prep_weights<<<48, 256>>>(Wq, Wk, W1);
    temporal_kernel<<<dim3(NN, NB), 256, SMEM_T>>>(
        x, W2, bq, bk, b1, b2, g0, beta0);
    spatial_kernel<<<dim3(NT, NB, 2), 256, SMEM_S>>>(
        adj, Theta, g1, beta1, out);
}

// round 15
// speedup vs baseline: 1.0018x; 1.0018x over previous
#include <cuda_runtime.h>

#define NB 16
#define ND 64
#define NN 200
#define NT 48
#define NH 8

// intermediate h = x^T + LN(temporal_out):  (B,N,T,D)
__device__ float g_h[NB * NN * NT * ND];

// pre-transposed weights (written by prep_weights each launch)
__device__ float2 g_wqkT[192 * 64];   // [(e*3+k)][d] -> (Wq, Wk)
__device__ float  g_w1T[64 * 64];     // [e][d] = W1[d][e]

__global__ void prep_weights(const float* __restrict__ Wq,
                             const float* __restrict__ Wk,
                             const float* __restrict__ W1)
{
    int i = blockIdx.x * 256 + threadIdx.x;
    if (i < 12288) {
        int r = i >> 6, d = i & 63;          // r = e*3+k
        float2 v;
        v.x = Wq[d * 192 + r];
        v.y = Wk[d * 192 + r];
        g_wqkT[i] = v;
    }
    if (i < 4096) {
        int e = i >> 6, d = i & 63;
        g_w1T[i] = W1[d * 64 + e];
    }
}

// ---- packed f32x2 helpers (Blackwell FFMA2 via PTX) ----
__device__ __forceinline__ float2 ffma2(float2 a, float2 b, float2 c) {
    float2 d;
    asm("fma.rn.f32x2 %0, %1, %2, %3;"
        : "=l"(*reinterpret_cast<unsigned long long*>(&d))
        : "l"(*reinterpret_cast<const unsigned long long*>(&a)),
          "l"(*reinterpret_cast<const unsigned long long*>(&b)),
          "l"(*reinterpret_cast<const unsigned long long*>(&c)));
    return d;
}
__device__ __forceinline__ float2 fdup(float s) { return make_float2(s, s); }
__device__ __forceinline__ float2 f2lo(float4 v) { return make_float2(v.x, v.y); }
__device__ __forceinline__ float2 f2hi(float4 v) { return make_float2(v.z, v.w); }

// ---------------------------------------------------------------------------
// Kernel 1: per (b, n). Fused conv1x3 q/k + v (single pass, packed f32x2),
// 8-head attention over T=48 (rows in registers, packed), W2 projection
// (packed dot over e), LayerNorm + residual -> g_h.
// smem floats: xs[64][52]@0, qs[64][52]@3328, ks[64][52]@6656, vs[48][68]@9984,
//              aos[48][68]@13248, ys[48][68]@16512, w2s[64][68]@19776
//              => 24128 floats = 96512 B  (2 blocks/SM)
// ---------------------------------------------------------------------------
__global__ void __launch_bounds__(256, 2) temporal_kernel(
    const float* __restrict__ x,  const float* __restrict__ W2,
    const float* __restrict__ bq, const float* __restrict__ bk,
    const float* __restrict__ b1, const float* __restrict__ b2,
    const float* __restrict__ g0, const float* __restrict__ beta0)
{
    extern __shared__ float sm[];
    float* xs   = sm;            // [64][52], col0/col49 zero pad
    float* qs   = sm + 3328;     // [64][52]
    float* ks   = sm + 6656;     // [64][52]
    float* vs   = sm + 9984;     // [48][68]
    float* aos  = sm + 13248;    // [48][68]
    float* ys   = sm + 16512;    // [48][68]
    float* w2s  = sm + 19776;    // [64][68]  W2 rows (row-major)

    const int n   = blockIdx.x;
    const int b   = blockIdx.y;
    const int tid = threadIdx.x;
    const int d   = tid & 63;
    const int t0  = (tid >> 6) * 12;
    const int lane = tid & 31;
    const int warp = tid >> 5;

    // load x tile: x[b][e][n][t] -> xs[e][1+t]
    const float* xbase = x + ((long)(b * 64) * 200 + n) * 48;
    for (int i = tid; i < 64 * 48; i += 256) {
        int e = i / 48, t = i % 48;
        xs[e * 52 + 1 + t] = xbase[(long)e * 9600 + t];
    }
    if (tid < 128) {
        int e = tid & 63;
        xs[e * 52 + ((tid < 64) ? 0 : 49)] = 0.f;
    }
    // stage W2 rows into smem (row-major, stride 68)
    for (int i = tid; i < 1024; i += 256) {
        int dd = i >> 4, e0 = (i & 15) * 4;
        *(float4*)(w2s + dd * 68 + e0) = *(const float4*)(W2 + dd * 64 + e0);
    }
    __syncthreads();   // xs, w2s ready

    // ---- fused conv1x3 q/k (packed over (q,k)) + v (scalar), single pass
    float2 qk[12];
    float  va[12];
    #pragma unroll
    for (int j = 0; j < 12; j++) { qk[j] = make_float2(0.f, 0.f); va[j] = 0.f; }

    #pragma unroll 2
    for (int el = 0; el < 64; el++) {
        const float2* wr = g_wqkT + el * 192 + d;
        float2 w0 = __ldg(wr);
        float2 w1 = __ldg(wr + 64);
        float2 w2 = __ldg(wr + 128);
        float  wv = __ldg(g_w1T + el * 64 + d);
        const float* xp = xs + el * 52 + t0;   // aligned; taps at [0..13]
        float4 x0 = *(const float4*)(xp);
        float4 x1 = *(const float4*)(xp + 4);
        float4 x2 = *(const float4*)(xp + 8);
        float4 x3 = *(const float4*)(xp + 12);
        float xv[16] = {x0.x,x0.y,x0.z,x0.w, x1.x,x1.y,x1.z,x1.w,
                        x2.x,x2.y,x2.z,x2.w, x3.x,x3.y,x3.z,x3.w};
        float2 xd[14];
        #pragma unroll
        for (int j = 0; j < 14; j++) xd[j] = fdup(xv[j]);
        #pragma unroll
        for (int j = 0; j < 12; j++) {
            qk[j] = ffma2(xd[j],     w0, qk[j]);
            qk[j] = ffma2(xd[j + 1], w1, qk[j]);
            qk[j] = ffma2(xd[j + 2], w2, qk[j]);
            va[j] += wv * xv[j + 1];
        }
    }
    {
        float bqv = __ldg(bq + d), bkv = __ldg(bk + d), b1v = __ldg(b1 + d);
        #pragma unroll
        for (int j = 0; j < 12; j++) {
            qs[d * 52 + t0 + j] = qk[j].x + bqv;
            ks[d * 52 + t0 + j] = qk[j].y + bkv;
            vs[(t0 + j) * 68 + d] = va[j] + b1v;
        }
    }
    __syncthreads();   // qs, ks, vs ready

    // ---- attention: thread = (head-half, t); two sweeps of 4 heads
    const float scale = 0.35355339059327373f; // 1/sqrt(8)
    if (tid < 192) {
        const int t  = tid % 48;
        const int hh = tid / 48;       // 0..3
        #pragma unroll
        for (int sw = 0; sw < 2; sw++) {
            const int hd = (sw * 4 + hh) * 8;
            float2 qd[8];
            #pragma unroll
            for (int dk = 0; dk < 8; dk++)
                qd[dk] = fdup(qs[(hd + dk) * 52 + t] * scale);
            float2 s2[24];
            #pragma unroll
            for (int i = 0; i < 24; i++) s2[i] = make_float2(0.f, 0.f);
            #pragma unroll
            for (int u4 = 0; u4 < 12; u4++) {
                #pragma unroll
                for (int dk = 0; dk < 8; dk++) {
                    float4 kv = *(const float4*)(ks + (hd + dk) * 52 + u4 * 4);
                    s2[2 * u4]     = ffma2(qd[dk], f2lo(kv), s2[2 * u4]);
                    s2[2 * u4 + 1] = ffma2(qd[dk], f2hi(kv), s2[2 * u4 + 1]);
                }
            }
            // softmax in registers
            float mx = -1e30f;
            #pragma unroll
            for (int i = 0; i < 24; i++)
                mx = fmaxf(mx, fmaxf(s2[i].x, s2[i].y));
            float sum = 0.f;
            #pragma unroll
            for (int i = 0; i < 24; i++) {
                s2[i].x = __expf(s2[i].x - mx);
                s2[i].y = __expf(s2[i].y - mx);
                sum += s2[i].x + s2[i].y;
            }
            float inv = 1.f / sum;
            // PV (packed over d)
            float2 a0l = make_float2(0.f, 0.f), a0h = a0l, a1l = a0l, a1h = a0l;
            #pragma unroll
            for (int i = 0; i < 24; i++) {
                int u = 2 * i;
                float2 p0 = fdup(s2[i].x), p1 = fdup(s2[i].y);
                float4 v00 = *(const float4*)(vs + u * 68 + hd);
                float4 v01 = *(const float4*)(vs + u * 68 + hd + 4);
                float4 v10 = *(const float4*)(vs + (u + 1) * 68 + hd);
                float4 v11 = *(const float4*)(vs + (u + 1) * 68 + hd + 4);
                a0l = ffma2(p0, f2lo(v00), a0l); a0h = ffma2(p0, f2hi(v00), a0h);
                a1l = ffma2(p0, f2lo(v01), a1l); a1h = ffma2(p0, f2hi(v01), a1h);
                a0l = ffma2(p1, f2lo(v10), a0l); a0h = ffma2(p1, f2hi(v10), a0h);
                a1l = ffma2(p1, f2lo(v11), a1l); a1h = ffma2(p1, f2hi(v11), a1h);
            }
            float4 o0 = make_float4(a0l.x * inv, a0l.y * inv, a0h.x * inv, a0h.y * inv);
            float4 o1 = make_float4(a1l.x * inv, a1l.y * inv, a1h.x * inv, a1h.y * inv);
            *(float4*)(aos + t * 68 + hd)     = o0;
            *(float4*)(aos + t * 68 + hd + 4) = o1;
        }
    }
    __syncthreads();

    // ---- y = ao @ W2^T + b2 (packed dot over e)
    {
        float2 ya2[12];
        #pragma unroll
        for (int j = 0; j < 12; j++) ya2[j] = make_float2(0.f, 0.f);
        #pragma unroll 4
        for (int e0 = 0; e0 < 64; e0 += 4) {
            float4 w = *(const float4*)(w2s + d * 68 + e0);
            float2 wl = f2lo(w), wh = f2hi(w);
            #pragma unroll
            for (int j = 0; j < 12; j++) {
                float4 a = *(const float4*)(aos + (t0 + j) * 68 + e0);
                ya2[j] = ffma2(wl, f2lo(a), ya2[j]);
                ya2[j] = ffma2(wh, f2hi(a), ya2[j]);
            }
        }
        float b2v = __ldg(b2 + d);
        #pragma unroll
        for (int j = 0; j < 12; j++)
            ys[(t0 + j) * 68 + d] = ya2[j].x + ya2[j].y + b2v;
    }
    __syncthreads();

    // ---- LayerNorm over d + residual x^T -> g_h
    float* hout = g_h + ((long)(b * 200 + n)) * 48 * 64;
    for (int t = warp; t < 48; t += 8) {
        float y1 = ys[t * 68 + lane];
        float y2 = ys[t * 68 + lane + 32];
        float s = y1 + y2;
        #pragma unroll
        for (int o = 16; o > 0; o >>= 1) s += __shfl_xor_sync(0xffffffffu, s, o);
        float mean = s * (1.f / 64.f);
        float d1 = y1 - mean, d2 = y2 - mean;
        float vv = d1 * d1 + d2 * d2;
        #pragma unroll
        for (int o = 16; o > 0; o >>= 1) vv += __shfl_xor_sync(0xffffffffu, vv, o);
        float rstd = rsqrtf(vv * (1.f / 64.f) + 1e-5f);
        float h1 = xs[lane * 52 + 1 + t]        + d1 * rstd * __ldg(g0 + lane)      + __ldg(beta0 + lane);
        float h2 = xs[(lane + 32) * 52 + 1 + t] + d2 * rstd * __ldg(g0 + lane + 32) + __ldg(beta0 + lane + 32);
        hout[t * 64 + lane]      = h1;
        hout[t * 64 + lane + 32] = h2;
    }
}

// ---------------------------------------------------------------------------
// Kernel 2: per (b, t, rowhalf). Spatial softmax-GCN, 100 rows/block.
// Packed f32x2 everywhere: scores/Theta = dot-over-dd pairs, agg = dup(P)*h.
// Softmax without max-shift; lane-local row-sums reduced once at the end.
// smem floats: hs[200][68]@0 (13600), S[100][68]@13600 (6800; ThS[64][68]
// overlays) => 20400 floats = 81600 B  (2 blocks/SM)
// ---------------------------------------------------------------------------
__global__ void __launch_bounds__(256, 2) spatial_kernel(
    const float* __restrict__ adj, const float* __restrict__ Theta,
    const float* __restrict__ g1,  const float* __restrict__ beta1,
    float* __restrict__ out)
{
    extern __shared__ float sm[];
    float* hs = sm;            // [200][68]
    float* S  = sm + 13600;    // [100][68] P buffer; later ThS[64][68] dd-major

    const int t = blockIdx.x, b = blockIdx.y;
    const int r0 = blockIdx.z * 100;
    const int tid = threadIdx.x;
    const int tx = tid & 15, ty = tid >> 4;

    const float* hbase = g_h + (long)b * 200 * 48 * 64 + (long)t * 64;
    for (int i = tid; i < 3200; i += 256) {
        int nn = i >> 4, d4 = (i & 15) * 4;
        *(float4*)(hs + nn * 68 + d4) = *(const float4*)(hbase + (long)nn * 3072 + d4);
    }

    int  nl[7], slc[7];
    bool rv[7];
    #pragma unroll
    for (int r = 0; r < 7; r++) {
        int v = ty + 16 * r;
        rv[r]  = (v < 100);
        slc[r] = rv[r] ? v : 99;
        nl[r]  = slc[r];
    }

    float2 agg2[7][2];
    float  rs[7];
    #pragma unroll
    for (int r = 0; r < 7; r++) {
        rs[r] = 0.f;
        agg2[r][0] = make_float2(0.f, 0.f);
        agg2[r][1] = make_float2(0.f, 0.f);
    }

    __syncthreads();   // hs ready

    for (int ci = 0; ci < 4; ci++) {
        const int m0 = ci * 64;
        const int MC = (ci == 3) ? 8 : 64;
        __syncwarp();  // P rows from previous chunk fully consumed

        // ---- scores (packed dot over dd): rows r0+nl[r], cols m0+tx+16c ----
        float2 sc2[7][4];
        #pragma unroll
        for (int r = 0; r < 7; r++)
            #pragma unroll
            for (int c = 0; c < 4; c++) sc2[r][c] = make_float2(0.f, 0.f);
        int  mc[4]; bool mv[4];
        #pragma unroll
        for (int c = 0; c < 4; c++) {
            int m = m0 + tx + 16 * c;
            mv[c] = (m < 200);
            mc[c] = mv[c] ? m : 199;
        }
        for (int dd = 0; dd < 64; dd += 4) {
            float4 bb[4];
            #pragma unroll
            for (int c = 0; c < 4; c++)
                bb[c] = *(const float4*)(hs + mc[c] * 68 + dd);
            #pragma unroll
            for (int r = 0; r < 7; r++) {
                float4 av = *(const float4*)(hs + (r0 + slc[r]) * 68 + dd);
                float2 al = f2lo(av), ah = f2hi(av);
                #pragma unroll
                for (int c = 0; c < 4; c++) {
                    sc2[r][c] = ffma2(al, f2lo(bb[c]), sc2[r][c]);
                    sc2[r][c] = ffma2(ah, f2hi(bb[c]), sc2[r][c]);
                }
            }
        }

        // ---- exp (no shift) + lane-local row-sum + P = e * adj ----
        #pragma unroll
        for (int r = 0; r < 7; r++) {
            float e[4];
            #pragma unroll
            for (int c = 0; c < 4; c++) {
                float sv = (sc2[r][c].x + sc2[r][c].y) * 0.125f;
                e[c] = mv[c] ? __expf(sv) : 0.f;
            }
            rs[r] += (e[0] + e[1]) + (e[2] + e[3]);
            if (rv[r]) {
                const float* arow = adj + (long)(r0 + nl[r]) * 200 + m0;
                #pragma unroll
                for (int c = 0; c < 4; c++)
                    if (mv[c])
                        S[nl[r] * 68 + tx + 16 * c] = e[c] * __ldg(arow + tx + 16 * c);
            }
        }
        __syncwarp();   // P rows visible within owning half-warp

        // ---- agg += P_chunk @ h_chunk (dup(P) * packed h, cols dd=4tx+c) ----
        for (int mb = 0; mb < MC; mb += 4) {
            float4 hb[4];
            #pragma unroll
            for (int j = 0; j < 4; j++)
                hb[j] = *(const float4*)(hs + (m0 + mb + j) * 68 + 4 * tx);
            #pragma unroll
            for (int r = 0; r < 7; r++) {
                float4 pw = *(const float4*)(S + slc[r] * 68 + mb);
                float2 p0 = fdup(pw.x), p1 = fdup(pw.y), p2 = fdup(pw.z), p3 = fdup(pw.w);
                agg2[r][0] = ffma2(p0, f2lo(hb[0]), agg2[r][0]);
                agg2[r][1] = ffma2(p0, f2hi(hb[0]), agg2[r][1]);
                agg2[r][0] = ffma2(p1, f2lo(hb[1]), agg2[r][0]);
                agg2[r][1] = ffma2(p1, f2hi(hb[1]), agg2[r][1]);
                agg2[r][0] = ffma2(p2, f2lo(hb[2]), agg2[r][0]);
                agg2[r][1] = ffma2(p2, f2hi(hb[2]), agg2[r][1]);
                agg2[r][0] = ffma2(p3, f2lo(hb[3]), agg2[r][0]);
                agg2[r][1] = ffma2(p3, f2hi(hb[3]), agg2[r][1]);
            }
        }
    }

    __syncthreads();   // done reading hs / S everywhere

    // reduce row-sums across the 16 lanes, finalize agg /= (rsum * sqrt(D))
    #pragma unroll
    for (int r = 0; r < 7; r++) {
        float s = rs[r];
        #pragma unroll
        for (int o = 8; o > 0; o >>= 1)
            s += __shfl_xor_sync(0xffffffffu, s, o, 16);
        float inv = 1.f / (s * 8.f);
        if (rv[r]) {
            float4 v = make_float4(agg2[r][0].x * inv, agg2[r][0].y * inv,
                                   agg2[r][1].x * inv, agg2[r][1].y * inv);
            *(float4*)(hs + nl[r] * 68 + 4 * tx) = v;
        }
    }
    // stage Theta dd-major: ThS[dd*68 + j] = Theta[j][dd]
    for (int i = tid; i < 4096; i += 256)
        S[(i & 63) * 68 + (i >> 6)] = Theta[i];
    __syncthreads();

    // G = relu(agg @ Theta^T): dup(agg) * packed Theta (lanes = j-pairs)
    float2 g2[7][2];
    #pragma unroll
    for (int r = 0; r < 7; r++) {
        g2[r][0] = make_float2(0.f, 0.f);
        g2[r][1] = make_float2(0.f, 0.f);
    }
    for (int dd = 0; dd < 64; dd += 4) {
        float4 tb[4];
        #pragma unroll
        for (int i = 0; i < 4; i++)
            tb[i] = *(const float4*)(S + (dd + i) * 68 + 4 * tx);
        #pragma unroll
        for (int r = 0; r < 7; r++) {
            float4 av = *(const float4*)(hs + slc[r] * 68 + dd);
            float2 a0 = fdup(av.x), a1 = fdup(av.y), a2 = fdup(av.z), a3 = fdup(av.w);
            g2[r][0] = ffma2(a0, f2lo(tb[0]), g2[r][0]);
            g2[r][1] = ffma2(a0, f2hi(tb[0]), g2[r][1]);
            g2[r][0] = ffma2(a1, f2lo(tb[1]), g2[r][0]);
            g2[r][1] = ffma2(a1, f2hi(tb[1]), g2[r][1]);
            g2[r][0] = ffma2(a2, f2lo(tb[2]), g2[r][0]);
            g2[r][1] = ffma2(a2, f2hi(tb[2]), g2[r][1]);
            g2[r][0] = ffma2(a3, f2lo(tb[3]), g2[r][0]);
            g2[r][1] = ffma2(a3, f2hi(tb[3]), g2[r][1]);
        }
    }
    float g[7][4];
    #pragma unroll
    for (int r = 0; r < 7; r++) {
        g[r][0] = fmaxf(g2[r][0].x, 0.f);
        g[r][1] = fmaxf(g2[r][0].y, 0.f);
        g[r][2] = fmaxf(g2[r][1].x, 0.f);
        g[r][3] = fmaxf(g2[r][1].y, 0.f);
    }

    // LayerNorm over j + residual (float4 gmem) + store
    float* obase = out + (long)b * 200 * 3072 + (long)t * 64;
    float4 g1v = *(const float4*)(g1 + 4 * tx);
    float4 b1v = *(const float4*)(beta1 + 4 * tx);
    #pragma unroll
    for (int r = 0; r < 7; r++) {
        if (!rv[r]) continue;
        int ng = r0 + nl[r];
        float s = g[r][0] + g[r][1] + g[r][2] + g[r][3];
        #pragma unroll
        for (int o = 8; o > 0; o >>= 1) s += __shfl_xor_sync(0xffffffffu, s, o, 16);
        float mean = s * (1.f / 64.f);
        float vv = 0.f;
        #pragma unroll
        for (int c = 0; c < 4; c++) { float dg = g[r][c] - mean; vv += dg * dg; }
        #pragma unroll
        for (int o = 8; o > 0; o >>= 1) vv += __shfl_xor_sync(0xffffffffu, vv, o, 16);
        float rstd = rsqrtf(vv * (1.f / 64.f) + 1e-5f);
        float4 hv = *(const float4*)(hbase + (long)ng * 3072 + 4 * tx);
        float4 ov;
        ov.x = hv.x + (g[r][0] - mean) * rstd * g1v.x + b1v.x;
        ov.y = hv.y + (g[r][1] - mean) * rstd * g1v.y + b1v.y;
        ov.z = hv.z + (g[r][2] - mean) * rstd * g1v.z + b1v.z;
        ov.w = hv.w + (g[r][3] - mean) * rstd * g1v.w + b1v.w;
        *(float4*)(obase + (long)ng * 3072 + 4 * tx) = ov;
    }
}

// ---------------------------------------------------------------------------
extern "C" void kernel_launch(void* const* d_in, const int* in_sizes, int n_in,
                              void* d_out, int out_size)
{
    const float* x     = (const float*)d_in[0];
    const float* adj   = (const float*)d_in[1];
    const float* Wq    = (const float*)d_in[2];
    const float* bq    = (const float*)d_in[3];
    const float* Wk    = (const float*)d_in[4];
    const float* bk    = (const float*)d_in[5];
    const float* W1    = (const float*)d_in[6];
    const float* b1    = (const float*)d_in[7];
    const float* W2    = (const float*)d_in[8];
    const float* b2    = (const float*)d_in[9];
    const float* Theta = (const float*)d_in[10];
    const float* g0    = (const float*)d_in[11];
    const float* beta0 = (const float*)d_in[12];
    const float* g1    = (const float*)d_in[13];
    const float* beta1 = (const float*)d_in[14];
    float* out = (float*)d_out;

    const int SMEM_T = 24128 * 4;   // 96512 B
    const int SMEM_S = 20400 * 4;   // 81600 B
    cudaFuncSetAttribute(temporal_kernel,
                         cudaFuncAttributeMaxDynamicSharedMemorySize, SMEM_T);
    cudaFuncSetAttribute(spatial_kernel,
                         cudaFuncAttributeMaxDynamicSharedMemorySize, SMEM_S);

    prep_weights<<<48, 256>>>(Wq, Wk, W1);
    temporal_kernel<<<dim3(NN, NB), 256, SMEM_T>>>(
        x, W2, bq, bk, b1, b2, g0, beta0);
    spatial_kernel<<<dim3(NT, NB, 2), 256, SMEM_S>>>(
        adj, Theta, g1, beta1, out);
}

// round 16
// speedup vs baseline: 1.0027x; 1.0010x over previous
#include <cuda_runtime.h>

#define NB 16
#define ND 64
#define NN 200
#define NT 48
#define NH 8

// intermediate h = x^T + LN(temporal_out):  (B,N,T,D)
__device__ float g_h[NB * NN * NT * ND];

// pre-transposed weights (written by prep_weights each launch)
__device__ float2 g_wqkT[192 * 64];   // [(e*3+k)][d] -> (Wq, Wk)
__device__ float  g_w1T[64 * 64];     // [e][d] = W1[d][e]

__global__ void prep_weights(const float* __restrict__ Wq,
                             const float* __restrict__ Wk,
                             const float* __restrict__ W1)
{
    int i = blockIdx.x * 256 + threadIdx.x;
    if (i < 12288) {
        int r = i >> 6, d = i & 63;          // r = e*3+k
        float2 v;
        v.x = Wq[d * 192 + r];
        v.y = Wk[d * 192 + r];
        g_wqkT[i] = v;
    }
    if (i < 4096) {
        int e = i >> 6, d = i & 63;
        g_w1T[i] = W1[d * 64 + e];
    }
}

// ---- packed f32x2 helpers (Blackwell FFMA2 via PTX) ----
__device__ __forceinline__ float2 ffma2(float2 a, float2 b, float2 c) {
    float2 d;
    asm("fma.rn.f32x2 %0, %1, %2, %3;"
        : "=l"(*reinterpret_cast<unsigned long long*>(&d))
        : "l"(*reinterpret_cast<const unsigned long long*>(&a)),
          "l"(*reinterpret_cast<const unsigned long long*>(&b)),
          "l"(*reinterpret_cast<const unsigned long long*>(&c)));
    return d;
}
__device__ __forceinline__ float2 fdup(float s) { return make_float2(s, s); }
__device__ __forceinline__ float2 f2lo(float4 v) { return make_float2(v.x, v.y); }
__device__ __forceinline__ float2 f2hi(float4 v) { return make_float2(v.z, v.w); }

// ---------------------------------------------------------------------------
// Kernel 1: per (b, n). Fused conv1x3 q/k + v (single pass, packed f32x2),
// 8-head attention over T=48 (rows in registers, packed), W2 projection
// (packed dot over e), LayerNorm + residual -> g_h.
// smem floats: xs[64][52]@0, qs[64][52]@3328, ks[64][52]@6656, vs[48][68]@9984,
//              aos[48][68]@13248, ys[48][68]@16512, w2s[64][68]@19776
//              => 24128 floats = 96512 B  (2 blocks/SM)
// ---------------------------------------------------------------------------
__global__ void __launch_bounds__(256, 2) temporal_kernel(
    const float* __restrict__ x,  const float* __restrict__ W2,
    const float* __restrict__ bq, const float* __restrict__ bk,
    const float* __restrict__ b1, const float* __restrict__ b2,
    const float* __restrict__ g0, const float* __restrict__ beta0)
{
    extern __shared__ float sm[];
    float* xs   = sm;            // [64][52], col0/col49 zero pad
    float* qs   = sm + 3328;     // [64][52]
    float* ks   = sm + 6656;     // [64][52]
    float* vs   = sm + 9984;     // [48][68]
    float* aos  = sm + 13248;    // [48][68]
    float* ys   = sm + 16512;    // [48][68]
    float* w2s  = sm + 19776;    // [64][68]  W2 rows (row-major)

    const int n   = blockIdx.x;
    const int b   = blockIdx.y;
    const int tid = threadIdx.x;
    const int d   = tid & 63;
    const int t0  = (tid >> 6) * 12;
    const int lane = tid & 31;
    const int warp = tid >> 5;

    // load x tile: x[b][e][n][t] -> xs[e][1+t]
    const float* xbase = x + ((long)(b * 64) * 200 + n) * 48;
    for (int i = tid; i < 64 * 48; i += 256) {
        int e = i / 48, t = i % 48;
        xs[e * 52 + 1 + t] = xbase[(long)e * 9600 + t];
    }
    if (tid < 128) {
        int e = tid & 63;
        xs[e * 52 + ((tid < 64) ? 0 : 49)] = 0.f;
    }
    // stage W2 rows into smem (row-major, stride 68)
    for (int i = tid; i < 1024; i += 256) {
        int dd = i >> 4, e0 = (i & 15) * 4;
        *(float4*)(w2s + dd * 68 + e0) = *(const float4*)(W2 + dd * 64 + e0);
    }
    __syncthreads();   // xs, w2s ready

    // ---- fused conv1x3 q/k (packed over (q,k)) + v (scalar), single pass
    float2 qk[12];
    float  va[12];
    #pragma unroll
    for (int j = 0; j < 12; j++) { qk[j] = make_float2(0.f, 0.f); va[j] = 0.f; }

    #pragma unroll 2
    for (int el = 0; el < 64; el++) {
        const float2* wr = g_wqkT + el * 192 + d;
        float2 w0 = __ldg(wr);
        float2 w1 = __ldg(wr + 64);
        float2 w2 = __ldg(wr + 128);
        float  wv = __ldg(g_w1T + el * 64 + d);
        const float* xp = xs + el * 52 + t0;   // aligned; taps at [0..13]
        float4 x0 = *(const float4*)(xp);
        float4 x1 = *(const float4*)(xp + 4);
        float4 x2 = *(const float4*)(xp + 8);
        float4 x3 = *(const float4*)(xp + 12);
        float xv[16] = {x0.x,x0.y,x0.z,x0.w, x1.x,x1.y,x1.z,x1.w,
                        x2.x,x2.y,x2.z,x2.w, x3.x,x3.y,x3.z,x3.w};
        float2 xd[14];
        #pragma unroll
        for (int j = 0; j < 14; j++) xd[j] = fdup(xv[j]);
        #pragma unroll
        for (int j = 0; j < 12; j++) {
            qk[j] = ffma2(xd[j],     w0, qk[j]);
            qk[j] = ffma2(xd[j + 1], w1, qk[j]);
            qk[j] = ffma2(xd[j + 2], w2, qk[j]);
            va[j] += wv * xv[j + 1];
        }
    }
    {
        float bqv = __ldg(bq + d), bkv = __ldg(bk + d), b1v = __ldg(b1 + d);
        #pragma unroll
        for (int j = 0; j < 12; j++) {
            qs[d * 52 + t0 + j] = qk[j].x + bqv;
            ks[d * 52 + t0 + j] = qk[j].y + bkv;
            vs[(t0 + j) * 68 + d] = va[j] + b1v;
        }
    }
    __syncthreads();   // qs, ks, vs ready

    // ---- attention: thread = (head-half, t); two sweeps of 4 heads
    const float scale = 0.35355339059327373f; // 1/sqrt(8)
    if (tid < 192) {
        const int t  = tid % 48;
        const int hh = tid / 48;       // 0..3
        #pragma unroll
        for (int sw = 0; sw < 2; sw++) {
            const int hd = (sw * 4 + hh) * 8;
            float2 qd[8];
            #pragma unroll
            for (int dk = 0; dk < 8; dk++)
                qd[dk] = fdup(qs[(hd + dk) * 52 + t] * scale);
            float2 s2[24];
            #pragma unroll
            for (int i = 0; i < 24; i++) s2[i] = make_float2(0.f, 0.f);
            #pragma unroll
            for (int u4 = 0; u4 < 12; u4++) {
                #pragma unroll
                for (int dk = 0; dk < 8; dk++) {
                    float4 kv = *(const float4*)(ks + (hd + dk) * 52 + u4 * 4);
                    s2[2 * u4]     = ffma2(qd[dk], f2lo(kv), s2[2 * u4]);
                    s2[2 * u4 + 1] = ffma2(qd[dk], f2hi(kv), s2[2 * u4 + 1]);
                }
            }
            // softmax in registers
            float mx = -1e30f;
            #pragma unroll
            for (int i = 0; i < 24; i++)
                mx = fmaxf(mx, fmaxf(s2[i].x, s2[i].y));
            float sum = 0.f;
            #pragma unroll
            for (int i = 0; i < 24; i++) {
                s2[i].x = __expf(s2[i].x - mx);
                s2[i].y = __expf(s2[i].y - mx);
                sum += s2[i].x + s2[i].y;
            }
            float inv = 1.f / sum;
            // PV (packed over d)
            float2 a0l = make_float2(0.f, 0.f), a0h = a0l, a1l = a0l, a1h = a0l;
            #pragma unroll
            for (int i = 0; i < 24; i++) {
                int u = 2 * i;
                float2 p0 = fdup(s2[i].x), p1 = fdup(s2[i].y);
                float4 v00 = *(const float4*)(vs + u * 68 + hd);
                float4 v01 = *(const float4*)(vs + u * 68 + hd + 4);
                float4 v10 = *(const float4*)(vs + (u + 1) * 68 + hd);
                float4 v11 = *(const float4*)(vs + (u + 1) * 68 + hd + 4);
                a0l = ffma2(p0, f2lo(v00), a0l); a0h = ffma2(p0, f2hi(v00), a0h);
                a1l = ffma2(p0, f2lo(v01), a1l); a1h = ffma2(p0, f2hi(v01), a1h);
                a0l = ffma2(p1, f2lo(v10), a0l); a0h = ffma2(p1, f2hi(v10), a0h);
                a1l = ffma2(p1, f2lo(v11), a1l); a1h = ffma2(p1, f2hi(v11), a1h);
            }
            float4 o0 = make_float4(a0l.x * inv, a0l.y * inv, a0h.x * inv, a0h.y * inv);
            float4 o1 = make_float4(a1l.x * inv, a1l.y * inv, a1h.x * inv, a1h.y * inv);
            *(float4*)(aos + t * 68 + hd)     = o0;
            *(float4*)(aos + t * 68 + hd + 4) = o1;
        }
    }
    __syncthreads();

    // ---- y = ao @ W2^T + b2 (packed dot over e)
    {
        float2 ya2[12];
        #pragma unroll
        for (int j = 0; j < 12; j++) ya2[j] = make_float2(0.f, 0.f);
        #pragma unroll 4
        for (int e0 = 0; e0 < 64; e0 += 4) {
            float4 w = *(const float4*)(w2s + d * 68 + e0);
            float2 wl = f2lo(w), wh = f2hi(w);
            #pragma unroll
            for (int j = 0; j < 12; j++) {
                float4 a = *(const float4*)(aos + (t0 + j) * 68 + e0);
                ya2[j] = ffma2(wl, f2lo(a), ya2[j]);
                ya2[j] = ffma2(wh, f2hi(a), ya2[j]);
            }
        }
        float b2v = __ldg(b2 + d);
        #pragma unroll
        for (int j = 0; j < 12; j++)
            ys[(t0 + j) * 68 + d] = ya2[j].x + ya2[j].y + b2v;
    }
    __syncthreads();

    // ---- LayerNorm over d + residual x^T -> g_h
    float* hout = g_h + ((long)(b * 200 + n)) * 48 * 64;
    for (int t = warp; t < 48; t += 8) {
        float y1 = ys[t * 68 + lane];
        float y2 = ys[t * 68 + lane + 32];
        float s = y1 + y2;
        #pragma unroll
        for (int o = 16; o > 0; o >>= 1) s += __shfl_xor_sync(0xffffffffu, s, o);
        float mean = s * (1.f / 64.f);
        float d1 = y1 - mean, d2 = y2 - mean;
        float vv = d1 * d1 + d2 * d2;
        #pragma unroll
        for (int o = 16; o > 0; o >>= 1) vv += __shfl_xor_sync(0xffffffffu, vv, o);
        float rstd = rsqrtf(vv * (1.f / 64.f) + 1e-5f);
        float h1 = xs[lane * 52 + 1 + t]        + d1 * rstd * __ldg(g0 + lane)      + __ldg(beta0 + lane);
        float h2 = xs[(lane + 32) * 52 + 1 + t] + d2 * rstd * __ldg(g0 + lane + 32) + __ldg(beta0 + lane + 32);
        hout[t * 64 + lane]      = h1;
        hout[t * 64 + lane + 32] = h2;
    }
}

// ---------------------------------------------------------------------------
// Kernel 2: per (b, t, rowhalf). Spatial softmax-GCN, 100 rows/block.
// Packed f32x2 everywhere: scores/Theta = dot-over-dd pairs, agg = dup(P)*h.
// Softmax without max-shift; lane-local row-sums reduced once at the end.
// smem floats: hs[200][68]@0 (13600), S[100][68]@13600 (6800; ThS[64][68]
// overlays) => 20400 floats = 81600 B  (2 blocks/SM)
// ---------------------------------------------------------------------------
__global__ void __launch_bounds__(256, 2) spatial_kernel(
    const float* __restrict__ adj, const float* __restrict__ Theta,
    const float* __restrict__ g1,  const float* __restrict__ beta1,
    float* __restrict__ out)
{
    extern __shared__ float sm[];
    float* hs = sm;            // [200][68]
    float* S  = sm + 13600;    // [100][68] P buffer; later ThS[64][68] dd-major

    const int t = blockIdx.x, b = blockIdx.y;
    const int r0 = blockIdx.z * 100;
    const int tid = threadIdx.x;
    const int tx = tid & 15, ty = tid >> 4;

    const float* hbase = g_h + (long)b * 200 * 48 * 64 + (long)t * 64;
    for (int i = tid; i < 3200; i += 256) {
        int nn = i >> 4, d4 = (i & 15) * 4;
        *(float4*)(hs + nn * 68 + d4) = *(const float4*)(hbase + (long)nn * 3072 + d4);
    }

    int  nl[7], slc[7];
    bool rv[7];
    #pragma unroll
    for (int r = 0; r < 7; r++) {
        int v = ty + 16 * r;
        rv[r]  = (v < 100);
        slc[r] = rv[r] ? v : 99;
        nl[r]  = slc[r];
    }

    float2 agg2[7][2];
    float  rs[7];
    #pragma unroll
    for (int r = 0; r < 7; r++) {
        rs[r] = 0.f;
        agg2[r][0] = make_float2(0.f, 0.f);
        agg2[r][1] = make_float2(0.f, 0.f);
    }

    __syncthreads();   // hs ready

    for (int ci = 0; ci < 4; ci++) {
        const int m0 = ci * 64;
        const int MC = (ci == 3) ? 8 : 64;
        __syncwarp();  // P rows from previous chunk fully consumed

        // ---- scores (packed dot over dd): rows r0+nl[r], cols m0+tx+16c ----
        float2 sc2[7][4];
        #pragma unroll
        for (int r = 0; r < 7; r++)
            #pragma unroll
            for (int c = 0; c < 4; c++) sc2[r][c] = make_float2(0.f, 0.f);
        int  mc[4]; bool mv[4];
        #pragma unroll
        for (int c = 0; c < 4; c++) {
            int m = m0 + tx + 16 * c;
            mv[c] = (m < 200);
            mc[c] = mv[c] ? m : 199;
        }
        for (int dd = 0; dd < 64; dd += 4) {
            float4 bb[4];
            #pragma unroll
            for (int c = 0; c < 4; c++)
                bb[c] = *(const float4*)(hs + mc[c] * 68 + dd);
            #pragma unroll
            for (int r = 0; r < 7; r++) {
                float4 av = *(const float4*)(hs + (r0 + slc[r]) * 68 + dd);
                float2 al = f2lo(av), ah = f2hi(av);
                #pragma unroll
                for (int c = 0; c < 4; c++) {
                    sc2[r][c] = ffma2(al, f2lo(bb[c]), sc2[r][c]);
                    sc2[r][c] = ffma2(ah, f2hi(bb[c]), sc2[r][c]);
                }
            }
        }

        // ---- exp (no shift) + lane-local row-sum + P = e * adj ----
        #pragma unroll
        for (int r = 0; r < 7; r++) {
            float e[4];
            #pragma unroll
            for (int c = 0; c < 4; c++) {
                float sv = (sc2[r][c].x + sc2[r][c].y) * 0.125f;
                e[c] = mv[c] ? __expf(sv) : 0.f;
            }
            rs[r] += (e[0] + e[1]) + (e[2] + e[3]);
            if (rv[r]) {
                const float* arow = adj + (long)(r0 + nl[r]) * 200 + m0;
                #pragma unroll
                for (int c = 0; c < 4; c++)
                    if (mv[c])
                        S[nl[r] * 68 + tx + 16 * c] = e[c] * __ldg(arow + tx + 16 * c);
            }
        }
        __syncwarp();   // P rows visible within owning half-warp

        // ---- agg += P_chunk @ h_chunk (dup(P) * packed h, cols dd=4tx+c) ----
        for (int mb = 0; mb < MC; mb += 4) {
            float4 hb[4];
            #pragma unroll
            for (int j = 0; j < 4; j++)
                hb[j] = *(const float4*)(hs + (m0 + mb + j) * 68 + 4 * tx);
            #pragma unroll
            for (int r = 0; r < 7; r++) {
                float4 pw = *(const float4*)(S + slc[r] * 68 + mb);
                float2 p0 = fdup(pw.x), p1 = fdup(pw.y), p2 = fdup(pw.z), p3 = fdup(pw.w);
                agg2[r][0] = ffma2(p0, f2lo(hb[0]), agg2[r][0]);
                agg2[r][1] = ffma2(p0, f2hi(hb[0]), agg2[r][1]);
                agg2[r][0] = ffma2(p1, f2lo(hb[1]), agg2[r][0]);
                agg2[r][1] = ffma2(p1, f2hi(hb[1]), agg2[r][1]);
                agg2[r][0] = ffma2(p2, f2lo(hb[2]), agg2[r][0]);
                agg2[r][1] = ffma2(p2, f2hi(hb[2]), agg2[r][1]);
                agg2[r][0] = ffma2(p3, f2lo(hb[3]), agg2[r][0]);
                agg2[r][1] = ffma2(p3, f2hi(hb[3]), agg2[r][1]);
            }
        }
    }

    __syncthreads();   // done reading hs / S everywhere

    // reduce row-sums across the 16 lanes, finalize agg /= (rsum * sqrt(D))
    #pragma unroll
    for (int r = 0; r < 7; r++) {
        float s = rs[r];
        #pragma unroll
        for (int o = 8; o > 0; o >>= 1)
            s += __shfl_xor_sync(0xffffffffu, s, o, 16);
        float inv = 1.f / (s * 8.f);
        if (rv[r]) {
            float4 v = make_float4(agg2[r][0].x * inv, agg2[r][0].y * inv,
                                   agg2[r][1].x * inv, agg2[r][1].y * inv);
            *(float4*)(hs + nl[r] * 68 + 4 * tx) = v;
        }
    }
    // stage Theta dd-major: ThS[dd*68 + j] = Theta[j][dd]
    for (int i = tid; i < 4096; i += 256)
        S[(i & 63) * 68 + (i >> 6)] = Theta[i];
    __syncthreads();

    // G = relu(agg @ Theta^T): dup(agg) * packed Theta (lanes = j-pairs)
    float2 g2[7][2];
    #pragma unroll
    for (int r = 0; r < 7; r++) {
        g2[r][0] = make_float2(0.f, 0.f);
        g2[r][1] = make_float2(0.f, 0.f);
    }
    for (int dd = 0; dd < 64; dd += 4) {
        float4 tb[4];
        #pragma unroll
        for (int i = 0; i < 4; i++)
            tb[i] = *(const float4*)(S + (dd + i) * 68 + 4 * tx);
        #pragma unroll
        for (int r = 0; r < 7; r++) {
            float4 av = *(const float4*)(hs + slc[r] * 68 + dd);
            float2 a0 = fdup(av.x), a1 = fdup(av.y), a2 = fdup(av.z), a3 = fdup(av.w);
            g2[r][0] = ffma2(a0, f2lo(tb[0]), g2[r][0]);
            g2[r][1] = ffma2(a0, f2hi(tb[0]), g2[r][1]);
            g2[r][0] = ffma2(a1, f2lo(tb[1]), g2[r][0]);
            g2[r][1] = ffma2(a1, f2hi(tb[1]), g2[r][1]);
            g2[r][0] = ffma2(a2, f2lo(tb[2]), g2[r][0]);
            g2[r][1] = ffma2(a2, f2hi(tb[2]), g2[r][1]);
            g2[r][0] = ffma2(a3, f2lo(tb[3]), g2[r][0]);
            g2[r][1] = ffma2(a3, f2hi(tb[3]), g2[r][1]);
        }
    }
    float g[7][4];
    #pragma unroll
    for (int r = 0; r < 7; r++) {
        g[r][0] = fmaxf(g2[r][0].x, 0.f);
        g[r][1] = fmaxf(g2[r][0].y, 0.f);
        g[r][2] = fmaxf(g2[r][1].x, 0.f);
        g[r][3] = fmaxf(g2[r][1].y, 0.f);
    }

    // LayerNorm over j + residual (float4 gmem) + store
    float* obase = out + (long)b * 200 * 3072 + (long)t * 64;
    float4 g1v = *(const float4*)(g1 + 4 * tx);
    float4 b1v = *(const float4*)(beta1 + 4 * tx);
    #pragma unroll
    for (int r = 0; r < 7; r++) {
        if (!rv[r]) continue;
        int ng = r0 + nl[r];
        float s = g[r][0] + g[r][1] + g[r][2] + g[r][3];
        #pragma unroll
        for (int o = 8; o > 0; o >>= 1) s += __shfl_xor_sync(0xffffffffu, s, o, 16);
        float mean = s * (1.f / 64.f);
        float vv = 0.f;
        #pragma unroll
        for (int c = 0; c < 4; c++) { float dg = g[r][c] - mean; vv += dg * dg; }
        #pragma unroll
        for (int o = 8; o > 0; o >>= 1) vv += __shfl_xor_sync(0xffffffffu, vv, o, 16);
        float rstd = rsqrtf(vv * (1.f / 64.f) + 1e-5f);
        float4 hv = *(const float4*)(hbase + (long)ng * 3072 + 4 * tx);
        float4 ov;
        ov.x = hv.x + (g[r][0] - mean) * rstd * g1v.x + b1v.x;
        ov.y = hv.y + (g[r][1] - mean) * rstd * g1v.y + b1v.y;
        ov.z = hv.z + (g[r][2] - mean) * rstd * g1v.z + b1v.z;
        ov.w = hv.w + (g[r][3] - mean) * rstd * g1v.w + b1v.w;
        *(float4*)(obase + (long)ng * 3072 + 4 * tx) = ov;
    }
}

// ---------------------------------------------------------------------------
extern "C" void kernel_launch(void* const* d_in, const int* in_sizes, int n_in,
                              void* d_out, int out_size)
{
    const float* x     = (const float*)d_in[0];
    const float* adj   = (const float*)d_in[1];
    const float* Wq    = (const float*)d_in[2];
    const float* bq    = (const float*)d_in[3];
    const float* Wk    = (const float*)d_in[4];
    const float* bk    = (const float*)d_in[5];
    const float* W1    = (const float*)d_in[6];
    const float* b1    = (const float*)d_in[7];
    const float* W2    = (const float*)d_in[8];
    const float* b2    = (const float*)d_in[9];
    const float* Theta = (const float*)d_in[10];
    const float* g0    = (const float*)d_in[11];
    const float* beta0 = (const float*)d_in[12];
    const float* g1    = (const float*)d_in[13];
    const float* beta1 = (const float*)d_in[14];
    float* out = (float*)d_out;

    const int SMEM_T = 24128 * 4;   // 96512 B
    const int SMEM_S = 20400 * 4;   // 81600 B
    cudaFuncSetAttribute(temporal_kernel,
                         cudaFuncAttributeMaxDynamicSharedMemorySize, SMEM_T);
    cudaFuncSetAttribute(spatial_kernel,
                         cudaFuncAttributeMaxDynamicSharedMemorySize, SMEM_S);

    prep_weights<<<48, 256>>>(Wq, Wk, W1);
    temporal_kernel<<<dim3(NN, NB), 256, SMEM_T>>>(
        x, W2, bq, bk, b1, b2, g0, beta0);
    spatial_kernel<<<dim3(NT, NB, 2), 256, SMEM_S>>>(
        adj, Theta, g1, beta1, out);
}